// round 5
// baseline (speedup 1.0000x reference)
#include <cuda_runtime.h>
#include <cstdint>

#define NN 100000
#define EE 3200000
#define DD 64
#define NPAIR (EE / 2)                        // 1,600,000
#define SCAN_B 256
#define NBLK ((NN + SCAN_B - 1) / SCAN_B)     // 391

// Static scratch (no allocation allowed)
__device__ int   g_deg[NN];
__device__ float g_dinv[NN];
__device__ int   g_ptr[NN + 1];
__device__ int   g_bsum[NBLK];
__device__ int   g_boff[NBLK];
__device__ int   g_fill[NN];
__device__ __align__(16) int2 g_sn[EE];       // sorted-by-target: {src, bitcast(norm)}
__device__ __align__(8)  int  g_tg[EE];       // sorted-by-target: target
__device__ __align__(16) float g_xa[NN * DD];
__device__ __align__(16) float g_xb[NN * DD];

// ---------------- preprocessing ----------------

__global__ void zero_counts_kernel() {
    int i = blockIdx.x * blockDim.x + threadIdx.x;
    if (i < NN) { g_deg[i] = 0; g_fill[i] = 0; }
}

__global__ void count_deg_kernel(const int* __restrict__ col32) {
    int e = blockIdx.x * blockDim.x + threadIdx.x;
    if (e < EE) {
        int c = col32[e];
        if (c >= 0 && c < NN) atomicAdd(&g_deg[c], 1);
    }
}

__global__ void dinv_kernel() {
    int i = blockIdx.x * blockDim.x + threadIdx.x;
    if (i < NN) {
        int d = g_deg[i];
        g_dinv[i] = (d > 0) ? rsqrtf((float)d) : 0.0f;
    }
}

__global__ void scan1_kernel() {
    __shared__ int s[SCAN_B];
    int tid = threadIdx.x;
    int gid = blockIdx.x * SCAN_B + tid;
    int v = (gid < NN) ? g_deg[gid] : 0;
    s[tid] = v;
    __syncthreads();
    #pragma unroll
    for (int off = 1; off < SCAN_B; off <<= 1) {
        int t = (tid >= off) ? s[tid - off] : 0;
        __syncthreads();
        s[tid] += t;
        __syncthreads();
    }
    if (gid < NN) g_ptr[gid] = s[tid] - v;
    if (tid == SCAN_B - 1) g_bsum[blockIdx.x] = s[tid];
}

__global__ void scan2_kernel() {
    __shared__ int s[512];
    int tid = threadIdx.x;
    int v = (tid < NBLK) ? g_bsum[tid] : 0;
    s[tid] = v;
    __syncthreads();
    #pragma unroll
    for (int off = 1; off < 512; off <<= 1) {
        int t = (tid >= off) ? s[tid - off] : 0;
        __syncthreads();
        s[tid] += t;
        __syncthreads();
    }
    if (tid < NBLK) g_boff[tid] = s[tid] - v;
    if (tid == NBLK - 1) g_ptr[NN] = s[tid];
}

__global__ void scan3_kernel() {
    int gid = blockIdx.x * SCAN_B + threadIdx.x;
    if (gid < NN) g_ptr[gid] += g_boff[blockIdx.x];
}

__global__ void fill_kernel(const int* __restrict__ row32,
                            const int* __restrict__ col32) {
    int e = blockIdx.x * blockDim.x + threadIdx.x;
    if (e < EE) {
        int r = row32[e];
        int c = col32[e];
        if (r >= 0 && r < NN && c >= 0 && c < NN) {
            float nrm = g_dinv[r] * g_dinv[c];
            int pos = g_ptr[c] + atomicAdd(&g_fill[c], 1);
            g_sn[pos] = make_int2(r, __float_as_int(nrm));
            g_tg[pos] = c;
        }
    }
}

__global__ void init_kernel(const float* __restrict__ emb, float* __restrict__ out) {
    int i = blockIdx.x * blockDim.x + threadIdx.x;
    if (i < NN * DD) out[i] = emb[i];
}

__global__ void zero_buf_kernel(float* __restrict__ p) {
    int i = blockIdx.x * blockDim.x + threadIdx.x;
    if (i < NN * DD) p[i] = 0.0f;
}

// ---------------- pair-merged flat scatter ----------------
// Thread = (pair p of 2 consecutive target-sorted edges, chunk c in 0..15).
// Fully unrolled: 1x LDG.128 (two {src,norm}), 1x LDG.64 (two targets),
// 2x LDG.128 gather, then 1 RED if targets match (p~0.97) else 2.
__device__ __forceinline__ void red4(float* dst, float4 v) {
    asm volatile("red.global.add.v4.f32 [%0], {%1,%2,%3,%4};"
                 :: "l"(dst), "f"(v.x), "f"(v.y), "f"(v.z), "f"(v.w)
                 : "memory");
}

__global__ __launch_bounds__(256) void pscatter_kernel(const float* __restrict__ xin,
                                                       float* __restrict__ xout) {
    int gid = blockIdx.x * blockDim.x + threadIdx.x;
    int c = gid & 15;
    int p = gid >> 4;
    if (p >= NPAIR) return;

    int4 sn = __ldg(reinterpret_cast<const int4*>(g_sn) + p);  // {src0,nrm0,src1,nrm1}
    int2 tg = __ldg(reinterpret_cast<const int2*>(g_tg) + p);  // {tgt0,tgt1}
    float n0 = __int_as_float(sn.y);
    float n1 = __int_as_float(sn.w);

    float4 v0 = __ldg(reinterpret_cast<const float4*>(xin + (size_t)sn.x * DD) + c);
    float4 v1 = __ldg(reinterpret_cast<const float4*>(xin + (size_t)sn.z * DD) + c);

    float4 m0, m1;
    m0.x = n0 * v0.x; m0.y = n0 * v0.y; m0.z = n0 * v0.z; m0.w = n0 * v0.w;
    m1.x = n1 * v1.x; m1.y = n1 * v1.y; m1.z = n1 * v1.z; m1.w = n1 * v1.w;

    float4* d0 = reinterpret_cast<float4*>(xout + (size_t)tg.x * DD) + c;
    if (tg.x == tg.y) {
        m0.x += m1.x; m0.y += m1.y; m0.z += m1.z; m0.w += m1.w;
        red4(reinterpret_cast<float*>(d0), m0);
    } else {
        red4(reinterpret_cast<float*>(d0), m0);
        float4* d1 = reinterpret_cast<float4*>(xout + (size_t)tg.y * DD) + c;
        red4(reinterpret_cast<float*>(d1), m1);
    }
}

// out += x
__global__ void accum_kernel(float* __restrict__ out, const float* __restrict__ x) {
    int i = blockIdx.x * blockDim.x + threadIdx.x;
    if (i < NN * DD) out[i] += x[i];
}

// out *= s
__global__ void scale_kernel(float* __restrict__ out, float s) {
    int i = blockIdx.x * blockDim.x + threadIdx.x;
    if (i < NN * DD) out[i] *= s;
}

// ---------------- launch ----------------

extern "C" void kernel_launch(void* const* d_in, const int* in_sizes, int n_in,
                              void* d_out, int out_size) {
    const float* emb = (const float*)d_in[0];
    const int* edge  = (const int*)d_in[1];   // [2, EE] int32
    const int* row32 = edge;
    const int* col32 = edge + EE;
    float* out = (float*)d_out;

    const int T = 256;
    int gN  = (NN + T - 1) / T;
    int gE  = (EE + T - 1) / T;
    int gND = (NN * DD + T - 1) / T;
    int gS  = (int)(((long long)NPAIR * 16 + T - 1) / T);

    // target-sorted edge list build
    zero_counts_kernel<<<gN, T>>>();
    count_deg_kernel<<<gE, T>>>(col32);
    dinv_kernel<<<gN, T>>>();
    scan1_kernel<<<NBLK, SCAN_B>>>();
    scan2_kernel<<<1, 512>>>();
    scan3_kernel<<<NBLK, SCAN_B>>>();
    fill_kernel<<<gE, T>>>(row32, col32);

    init_kernel<<<gND, T>>>(emb, out);

    // Layer 1: emb -> xa ; out += xa
    zero_buf_kernel<<<gND, T>>>(g_xa);
    pscatter_kernel<<<gS, T>>>(emb, g_xa);
    accum_kernel<<<gND, T>>>(out, g_xa);

    // Layer 2: xa -> xb ; out += xb
    zero_buf_kernel<<<gND, T>>>(g_xb);
    pscatter_kernel<<<gS, T>>>(g_xa, g_xb);
    accum_kernel<<<gND, T>>>(out, g_xb);

    // Layer 3: xb -> out directly, then /4
    pscatter_kernel<<<gS, T>>>(g_xb, out);
    scale_kernel<<<gND, T>>>(out, 0.25f);
}

// round 8
// speedup vs baseline: 1.4650x; 1.4650x over previous
#include <cuda_runtime.h>
#include <cstdint>

#define NN 100000
#define EE 3200000
#define DD 64
#define SCAN_B 256
#define NBLK ((NN + SCAN_B - 1) / SCAN_B)     // 391

// Static scratch (no allocation allowed)
__device__ int   g_deg[NN];
__device__ float g_dinv[NN];
__device__ int   g_ptr[NN + 1];
__device__ int   g_bsum[NBLK];
__device__ int   g_boff[NBLK];
__device__ int   g_fill[NN];
__device__ __align__(16) int2  g_sn[EE];      // CSR payload: {src, bitcast(norm)}
__device__ __align__(16) float g_xa[NN * DD];
__device__ __align__(16) float g_xb[NN * DD];

// ---------------- CSR build ----------------

__global__ void zero_counts_kernel() {
    int i = blockIdx.x * blockDim.x + threadIdx.x;
    if (i < NN) { g_deg[i] = 0; g_fill[i] = 0; }
}

__global__ void count_deg_kernel(const int* __restrict__ col32) {
    int e = blockIdx.x * blockDim.x + threadIdx.x;
    if (e < EE) {
        int c = col32[e];
        if (c >= 0 && c < NN) atomicAdd(&g_deg[c], 1);
    }
}

__global__ void dinv_kernel() {
    int i = blockIdx.x * blockDim.x + threadIdx.x;
    if (i < NN) {
        int d = g_deg[i];
        g_dinv[i] = (d > 0) ? rsqrtf((float)d) : 0.0f;
    }
}

__global__ void scan1_kernel() {
    __shared__ int s[SCAN_B];
    int tid = threadIdx.x;
    int gid = blockIdx.x * SCAN_B + tid;
    int v = (gid < NN) ? g_deg[gid] : 0;
    s[tid] = v;
    __syncthreads();
    #pragma unroll
    for (int off = 1; off < SCAN_B; off <<= 1) {
        int t = (tid >= off) ? s[tid - off] : 0;
        __syncthreads();
        s[tid] += t;
        __syncthreads();
    }
    if (gid < NN) g_ptr[gid] = s[tid] - v;
    if (tid == SCAN_B - 1) g_bsum[blockIdx.x] = s[tid];
}

__global__ void scan2_kernel() {
    __shared__ int s[512];
    int tid = threadIdx.x;
    int v = (tid < NBLK) ? g_bsum[tid] : 0;
    s[tid] = v;
    __syncthreads();
    #pragma unroll
    for (int off = 1; off < 512; off <<= 1) {
        int t = (tid >= off) ? s[tid - off] : 0;
        __syncthreads();
        s[tid] += t;
        __syncthreads();
    }
    if (tid < NBLK) g_boff[tid] = s[tid] - v;
    if (tid == NBLK - 1) g_ptr[NN] = s[tid];
}

__global__ void scan3_kernel() {
    int gid = blockIdx.x * SCAN_B + threadIdx.x;
    if (gid < NN) g_ptr[gid] += g_boff[blockIdx.x];
}

__global__ void fill_kernel(const int* __restrict__ row32,
                            const int* __restrict__ col32) {
    int e = blockIdx.x * blockDim.x + threadIdx.x;
    if (e < EE) {
        int r = row32[e];
        int c = col32[e];
        if (r >= 0 && r < NN && c >= 0 && c < NN) {
            float nrm = g_dinv[r] * g_dinv[c];
            int pos = g_ptr[c] + atomicAdd(&g_fill[c], 1);
            g_sn[pos] = make_int2(r, __float_as_int(nrm));
        }
    }
}

// out = emb  (plain stores only into d_out)
__global__ void init_kernel(const float* __restrict__ emb, float* __restrict__ out) {
    int i = blockIdx.x * blockDim.x + threadIdx.x;
    if (i < NN * DD) out[i] = emb[i];
}

// ---------------- CSR gather layer (no atomics, no shfl) ----------------
// One thread per (node, 16B chunk). Flat unrollable loop over the node's
// incoming edges: payload int2 (half-warp broadcast) + LDG.128 gather + 4 FMA.
// Epilogue: optional x_new store + fused out = (out + x_new) * scale.
__global__ __launch_bounds__(256) void gather_kernel(const float* __restrict__ xin,
                                                     float* __restrict__ xnew,
                                                     float* __restrict__ out,
                                                     float scale) {
    int gid = blockIdx.x * blockDim.x + threadIdx.x;
    if (gid >= NN * 16) return;
    int node = gid >> 4;
    int c    = gid & 15;

    int js = g_ptr[node];
    int je = g_ptr[node + 1];

    float4 acc = make_float4(0.f, 0.f, 0.f, 0.f);
    #pragma unroll 4
    for (int j = js; j < je; j++) {
        int2 p = __ldg(&g_sn[j]);
        float nm = __int_as_float(p.y);
        float4 v = __ldg(reinterpret_cast<const float4*>(xin + (size_t)p.x * DD) + c);
        acc.x = fmaf(nm, v.x, acc.x);
        acc.y = fmaf(nm, v.y, acc.y);
        acc.z = fmaf(nm, v.z, acc.z);
        acc.w = fmaf(nm, v.w, acc.w);
    }

    size_t o = (size_t)node * DD + (size_t)c * 4;
    if (xnew) *reinterpret_cast<float4*>(xnew + o) = acc;

    float4 ov = *reinterpret_cast<const float4*>(out + o);
    ov.x = (ov.x + acc.x) * scale;
    ov.y = (ov.y + acc.y) * scale;
    ov.z = (ov.z + acc.z) * scale;
    ov.w = (ov.w + acc.w) * scale;
    *reinterpret_cast<float4*>(out + o) = ov;
}

// ---------------- launch ----------------

extern "C" void kernel_launch(void* const* d_in, const int* in_sizes, int n_in,
                              void* d_out, int out_size) {
    const float* emb = (const float*)d_in[0];
    const int* edge  = (const int*)d_in[1];   // [2, EE] int32
    const int* row32 = edge;
    const int* col32 = edge + EE;
    float* out = (float*)d_out;

    const int T = 256;
    int gN  = (NN + T - 1) / T;
    int gE  = (EE + T - 1) / T;
    int gND = (NN * DD + T - 1) / T;
    int gG  = (NN * 16 + T - 1) / T;   // 1.6M threads

    // CSR build (sorted-by-target; safe for gather — no atomics downstream)
    zero_counts_kernel<<<gN, T>>>();
    count_deg_kernel<<<gE, T>>>(col32);
    dinv_kernel<<<gN, T>>>();
    scan1_kernel<<<NBLK, SCAN_B>>>();
    scan2_kernel<<<1, 512>>>();
    scan3_kernel<<<NBLK, SCAN_B>>>();
    fill_kernel<<<gE, T>>>(row32, col32);

    // out = emb
    init_kernel<<<gND, T>>>(emb, out);

    // Layer 1: x1 = A*emb      ; out += x1
    gather_kernel<<<gG, T>>>(emb,  g_xa, out, 1.0f);
    // Layer 2: x2 = A*x1       ; out += x2
    gather_kernel<<<gG, T>>>(g_xa, g_xb, out, 1.0f);
    // Layer 3: x3 = A*x2       ; out = (out + x3) / 4
    gather_kernel<<<gG, T>>>(g_xb, nullptr, out, 0.25f);
}

// round 11
// speedup vs baseline: 19.4803x; 13.2969x over previous
#include <cuda_runtime.h>
#include <cstdint>

#define NN 100000
#define EE 3200000
#define DD 64

// Scratch (static __device__ arrays; no allocation allowed)
__device__ int   g_deg[NN];
__device__ float g_dinv[NN];
__device__ float g_norm[EE];
__device__ int   g_row[EE];
__device__ int   g_col[EE];
__device__ __align__(16) float g_xa[NN * DD];
__device__ __align__(16) float g_xb[NN * DD];

__global__ void zero_deg_kernel() {
    int i = blockIdx.x * blockDim.x + threadIdx.x;
    if (i < NN) g_deg[i] = 0;
}

__global__ void count_deg_kernel(const int* __restrict__ col32) {
    int e = blockIdx.x * blockDim.x + threadIdx.x;
    if (e < EE) {
        int c = col32[e];
        if (c >= 0 && c < NN) atomicAdd(&g_deg[c], 1);
    }
}

__global__ void dinv_kernel() {
    int i = blockIdx.x * blockDim.x + threadIdx.x;
    if (i < NN) {
        int d = g_deg[i];
        g_dinv[i] = (d > 0) ? rsqrtf((float)d) : 0.0f;
    }
}

__global__ void prep_edges_kernel(const int* __restrict__ row32,
                                  const int* __restrict__ col32) {
    int e = blockIdx.x * blockDim.x + threadIdx.x;
    if (e < EE) {
        int r = row32[e];
        int c = col32[e];
        // defensive clamp: out-of-range edges become self-edges on node 0 with 0 weight
        bool ok = (r >= 0 && r < NN && c >= 0 && c < NN);
        g_row[e] = ok ? r : 0;
        g_col[e] = ok ? c : 0;
        g_norm[e] = ok ? g_dinv[r] * g_dinv[c] : 0.0f;
    }
}

// acc (d_out) = emb ; x_a = emb
__global__ void init_kernel(const float* __restrict__ emb, float* __restrict__ out) {
    int i = blockIdx.x * blockDim.x + threadIdx.x;
    if (i < NN * DD) {
        float v = emb[i];
        g_xa[i] = v;
        out[i] = v;
    }
}

// zero one of the ping-pong buffers. which==0 -> zero g_xb, which==1 -> zero g_xa
__global__ void zero_x_kernel(int which) {
    int i = blockIdx.x * blockDim.x + threadIdx.x;
    if (i < NN * DD) {
        if (which == 0) g_xb[i] = 0.0f;
        else            g_xa[i] = 0.0f;
    }
}

// Edge-parallel scatter: one thread per (edge, 4-float chunk).
// dir==0: read g_xa, scatter into g_xb ; dir==1: read g_xb, scatter into g_xa
template <int DIR>
__global__ __launch_bounds__(256) void scatter_kernel() {
    long long idx = (long long)blockIdx.x * blockDim.x + threadIdx.x;
    if (idx >= (long long)EE * 16) return;
    int e = (int)(idx >> 4);
    int c = (int)(idx & 15);

    int r  = __ldg(&g_row[e]);
    int co = __ldg(&g_col[e]);
    float nm = __ldg(&g_norm[e]);

    const float* xin  = DIR == 0 ? g_xa : g_xb;
    float*       xout = DIR == 0 ? g_xb : g_xa;

    const float4* src = reinterpret_cast<const float4*>(xin + (long long)r * DD) + c;
    float4 v = __ldg(src);
    v.x *= nm; v.y *= nm; v.z *= nm; v.w *= nm;

    float4* dst = reinterpret_cast<float4*>(xout + (long long)co * DD) + c;
    asm volatile("red.global.add.v4.f32 [%0], {%1,%2,%3,%4};"
                 :: "l"(dst), "f"(v.x), "f"(v.y), "f"(v.z), "f"(v.w)
                 : "memory");
}

// out = (out + x) * scale, where x = (which==0 ? g_xb : g_xa)
__global__ void accum_kernel(float* __restrict__ out, int which, float scale) {
    int i = blockIdx.x * blockDim.x + threadIdx.x;
    if (i < NN * DD) {
        float xv = (which == 0) ? g_xb[i] : g_xa[i];
        out[i] = (out[i] + xv) * scale;
    }
}

extern "C" void kernel_launch(void* const* d_in, const int* in_sizes, int n_in,
                              void* d_out, int out_size) {
    const float* emb = (const float*)d_in[0];
    const int* edge = (const int*)d_in[1];  // [2, EE] int32 (JAX x64-disabled downcast)
    const int* row32 = edge;
    const int* col32 = edge + EE;
    float* out = (float*)d_out;

    const int T = 256;
    int gN  = (NN + T - 1) / T;
    int gE  = (EE + T - 1) / T;
    int gND = (NN * DD + T - 1) / T;
    int gS  = (int)(((long long)EE * 16 + T - 1) / T);

    // --- preprocessing (per call; graph-capturable kernel launches only) ---
    zero_deg_kernel<<<gN, T>>>();
    count_deg_kernel<<<gE, T>>>(col32);
    dinv_kernel<<<gN, T>>>();
    prep_edges_kernel<<<gE, T>>>(row32, col32);
    init_kernel<<<gND, T>>>(emb, out);

    // --- layer 0: xa -> xb ---
    zero_x_kernel<<<gND, T>>>(0);
    scatter_kernel<0><<<gS, T>>>();
    accum_kernel<<<gND, T>>>(out, 0, 1.0f);

    // --- layer 1: xb -> xa ---
    zero_x_kernel<<<gND, T>>>(1);
    scatter_kernel<1><<<gS, T>>>();
    accum_kernel<<<gND, T>>>(out, 1, 1.0f);

    // --- layer 2: xa -> xb (fold /4 into last accumulate) ---
    zero_x_kernel<<<gND, T>>>(0);
    scatter_kernel<0><<<gS, T>>>();
    accum_kernel<<<gND, T>>>(out, 0, 0.25f);
}

// round 12
// speedup vs baseline: 21.2281x; 1.0897x over previous
#include <cuda_runtime.h>
#include <cstdint>

#define NN 100000
#define EE 3200000
#define DD 64
#define ND4 (NN * DD / 4)   // 1,600,000 float4 elements

// Scratch (static __device__ arrays; no allocation allowed)
__device__ int   g_deg[NN];
__device__ float g_dinv[NN];
__device__ float g_norm[EE];
__device__ int   g_row[EE];
__device__ int   g_col[EE];
__device__ __align__(16) float g_xa[NN * DD];
__device__ __align__(16) float g_xb[NN * DD];

__global__ void zero_deg_kernel() {
    int i = blockIdx.x * blockDim.x + threadIdx.x;
    if (i < NN) g_deg[i] = 0;
}

__global__ void count_deg_kernel(const int* __restrict__ col32) {
    int e = blockIdx.x * blockDim.x + threadIdx.x;
    if (e < EE) {
        int c = col32[e];
        if (c >= 0 && c < NN) atomicAdd(&g_deg[c], 1);
    }
}

__global__ void dinv_kernel() {
    int i = blockIdx.x * blockDim.x + threadIdx.x;
    if (i < NN) {
        int d = g_deg[i];
        g_dinv[i] = (d > 0) ? rsqrtf((float)d) : 0.0f;
    }
}

__global__ void prep_edges_kernel(const int* __restrict__ row32,
                                  const int* __restrict__ col32) {
    int e = blockIdx.x * blockDim.x + threadIdx.x;
    if (e < EE) {
        int r = row32[e];
        int c = col32[e];
        bool ok = (r >= 0 && r < NN && c >= 0 && c < NN);
        g_row[e] = ok ? r : 0;
        g_col[e] = ok ? c : 0;
        g_norm[e] = ok ? g_dinv[r] * g_dinv[c] : 0.0f;
    }
}

// acc (d_out) = emb ; x_a = emb   (float4 granularity)
__global__ void init_kernel(const float* __restrict__ emb, float* __restrict__ out) {
    int i = blockIdx.x * blockDim.x + threadIdx.x;
    if (i < ND4) {
        float4 v = reinterpret_cast<const float4*>(emb)[i];
        reinterpret_cast<float4*>(g_xa)[i] = v;
        reinterpret_cast<float4*>(out)[i] = v;
    }
}

// zero one ping buffer (float4 granularity). which==0 -> g_xb, which==1 -> g_xa
__global__ void zero_x_kernel(int which) {
    int i = blockIdx.x * blockDim.x + threadIdx.x;
    if (i < ND4) {
        float4 z = make_float4(0.f, 0.f, 0.f, 0.f);
        if (which == 0) reinterpret_cast<float4*>(g_xb)[i] = z;
        else            reinterpret_cast<float4*>(g_xa)[i] = z;
    }
}

// Edge-parallel scatter: one thread per (edge, 4-float chunk). UNCHANGED from anchor.
template <int DIR>
__global__ __launch_bounds__(256) void scatter_kernel() {
    long long idx = (long long)blockIdx.x * blockDim.x + threadIdx.x;
    if (idx >= (long long)EE * 16) return;
    int e = (int)(idx >> 4);
    int c = (int)(idx & 15);

    int r  = __ldg(&g_row[e]);
    int co = __ldg(&g_col[e]);
    float nm = __ldg(&g_norm[e]);

    const float* xin  = DIR == 0 ? g_xa : g_xb;
    float*       xout = DIR == 0 ? g_xb : g_xa;

    const float4* src = reinterpret_cast<const float4*>(xin + (long long)r * DD) + c;
    float4 v = __ldg(src);
    v.x *= nm; v.y *= nm; v.z *= nm; v.w *= nm;

    float4* dst = reinterpret_cast<float4*>(xout + (long long)co * DD) + c;
    asm volatile("red.global.add.v4.f32 [%0], {%1,%2,%3,%4};"
                 :: "l"(dst), "f"(v.x), "f"(v.y), "f"(v.z), "f"(v.w)
                 : "memory");
}

// out = (out + x) * scale  (float4 granularity), x = (which==0 ? g_xb : g_xa)
__global__ void accum_kernel(float* __restrict__ out, int which, float scale) {
    int i = blockIdx.x * blockDim.x + threadIdx.x;
    if (i < ND4) {
        float4 xv = (which == 0) ? reinterpret_cast<const float4*>(g_xb)[i]
                                 : reinterpret_cast<const float4*>(g_xa)[i];
        float4 ov = reinterpret_cast<const float4*>(out)[i];
        ov.x = (ov.x + xv.x) * scale;
        ov.y = (ov.y + xv.y) * scale;
        ov.z = (ov.z + xv.z) * scale;
        ov.w = (ov.w + xv.w) * scale;
        reinterpret_cast<float4*>(out)[i] = ov;
    }
}

extern "C" void kernel_launch(void* const* d_in, const int* in_sizes, int n_in,
                              void* d_out, int out_size) {
    const float* emb = (const float*)d_in[0];
    const int* edge = (const int*)d_in[1];  // [2, EE] int32
    const int* row32 = edge;
    const int* col32 = edge + EE;
    float* out = (float*)d_out;

    const int T = 256;
    int gN  = (NN + T - 1) / T;
    int gE  = (EE + T - 1) / T;
    int gV  = (ND4 + T - 1) / T;           // float4 elementwise grid
    int gS  = (int)(((long long)EE * 16 + T - 1) / T);

    // --- preprocessing (unchanged) ---
    zero_deg_kernel<<<gN, T>>>();
    count_deg_kernel<<<gE, T>>>(col32);
    dinv_kernel<<<gN, T>>>();
    prep_edges_kernel<<<gE, T>>>(row32, col32);
    init_kernel<<<gV, T>>>(emb, out);

    // --- layer 0: xa -> xb ---
    zero_x_kernel<<<gV, T>>>(0);
    scatter_kernel<0><<<gS, T>>>();
    accum_kernel<<<gV, T>>>(out, 0, 1.0f);

    // --- layer 1: xb -> xa ---
    zero_x_kernel<<<gV, T>>>(1);
    scatter_kernel<1><<<gS, T>>>();
    accum_kernel<<<gV, T>>>(out, 1, 1.0f);

    // --- layer 2: xa -> xb (fold /4 into last accumulate) ---
    zero_x_kernel<<<gV, T>>>(0);
    scatter_kernel<0><<<gS, T>>>();
    accum_kernel<<<gV, T>>>(out, 0, 0.25f);
}